// round 2
// baseline (speedup 1.0000x reference)
#include <cuda_runtime.h>
#include <cstdint>

// CombineEmbeddings: out[b,s,:] = (idx[b,s] >= 0) ? patch[b, idx[b,s], :]
//                                                 : word[b, s, :]
// Shapes (fixed): B=4, S=4096, P=2048, H=4096, fp32.
// Pure HBM-bound row copy: 256 MiB read + 256 MiB write, zero reuse.
// R2: 256-bit LDG/STG (sm_103a) + front-batched loads for deeper MLP.

#define CE_B 4
#define CE_S 4096
#define CE_P 2048
#define CE_H 4096

__device__ __forceinline__ void ldg256(const float* p, uint32_t r[8])
{
    asm volatile(
        "ld.global.nc.v8.b32 {%0,%1,%2,%3,%4,%5,%6,%7}, [%8];"
        : "=r"(r[0]), "=r"(r[1]), "=r"(r[2]), "=r"(r[3]),
          "=r"(r[4]), "=r"(r[5]), "=r"(r[6]), "=r"(r[7])
        : "l"(p));
}

__device__ __forceinline__ void stg256(float* p, const uint32_t r[8])
{
    asm volatile(
        "st.global.v8.b32 [%0], {%1,%2,%3,%4,%5,%6,%7,%8};"
        :: "l"(p),
           "r"(r[0]), "r"(r[1]), "r"(r[2]), "r"(r[3]),
           "r"(r[4]), "r"(r[5]), "r"(r[6]), "r"(r[7])
        : "memory");
}

__global__ void __launch_bounds__(256)
combine_embeddings_kernel(const float* __restrict__ word,
                          const float* __restrict__ patch,
                          const int*   __restrict__ idx,
                          float*       __restrict__ out)
{
    const int row = blockIdx.x;               // 0 .. B*S-1
    const int b   = row >> 12;                // row / S  (S = 4096)
    const int i   = __ldg(idx + row);

    const float* __restrict__ src =
        (i >= 0) ? (patch + ((int64_t)b * CE_P + i) * CE_H)
                 : (word  + (int64_t)row * CE_H);
    float* __restrict__ dst = out + (int64_t)row * CE_H;

    // Row = 16 KB. 256 threads x 32 B = 8 KB per pass, 2 passes.
    // Front-batch both 256-bit loads so 64 B/thread is in flight before
    // the first store's dependency binds.
    const int e = threadIdx.x * 8;            // float offset of 32B chunk
    uint32_t a[8], c[8];
    ldg256(src + e,               a);
    ldg256(src + e + CE_H / 2,    c);         // +2048 floats = +8 KB
    stg256(dst + e,               a);
    stg256(dst + e + CE_H / 2,    c);
}

extern "C" void kernel_launch(void* const* d_in, const int* in_sizes, int n_in,
                              void* d_out, int out_size)
{
    const float* word  = (const float*)d_in[0];   // [B, S, H] fp32
    const float* patch = (const float*)d_in[1];   // [B, P, H] fp32
    const int*   idx   = (const int*)d_in[2];     // [B, S] int32
    float*       out   = (float*)d_out;           // [B, S, H] fp32

    const int rows = CE_B * CE_S;                 // 16384
    combine_embeddings_kernel<<<rows, 256>>>(word, patch, idx, out);
}